// round 11
// baseline (speedup 1.0000x reference)
#include <cuda_runtime.h>

// QuantumFeatureExtractor — analytic collapse, vectorized fp32 path.
// TERMINAL configuration (R6 best: 4.61us; all variants within ±0.15us noise
// of the ~4us graph-replay/launch floor — ncu shows DRAM/L2/all pipes ~0%).
//
// Math: circuit applies one RX(x[b,i]+theta[i]) per distinct qubit to |0..0>,
// so the state stays a product state and <Z_i> = cos(x[b,i] + theta[i]).
// The 2^20-dim statevector in the reference collapses to 320 cosines.
//
// Frozen lessons:
//  - fp64 cos: +1us on the weak FP64 pipe (R1) — use MUFU __cosf
//    (|angle| < ~7, abs err ~1e-6, vs 1e-3 rel budget).
//  - float4 load of theta (d_in[1], 80B tensor): alignment trap that kills
//    the run (R4/R5) — theta stays scalar-loaded.
//  - folding tail work into fewer warps lengthens the slowest warp's serial
//    path, +1us (R7) — one float4 per thread, 3 warps.
//  - index-math micro-trims (%5 removal via 2D block, float2 shape): all
//    within noise (R9/R10).

#define BATCH 16
#define N_QUBITS 20
#define TOTAL (BATCH * N_QUBITS)   // 320
#define NTHREADS (TOTAL / 4)       // 80 threads = 3 warps

__global__ __launch_bounds__(NTHREADS, 1)
void qfe_kernel(const float4* __restrict__ x4,
                const float* __restrict__ theta,
                float4* __restrict__ out4) {
    int t = threadIdx.x;           // 0..79
    float4 v = x4[t];
    // element base = 4t; q0 = (4t) % 20 is a multiple of 4 in [0,16],
    // so the 4 thetas for this thread are theta[q0..q0+3], no wraparound.
    int q0 = (t % (N_QUBITS / 4)) * 4;   // (t % 5) * 4
    float4 r;
    r.x = __cosf(v.x + theta[q0 + 0]);
    r.y = __cosf(v.y + theta[q0 + 1]);
    r.z = __cosf(v.z + theta[q0 + 2]);
    r.w = __cosf(v.w + theta[q0 + 3]);
    out4[t] = r;
}

extern "C" void kernel_launch(void* const* d_in, const int* in_sizes, int n_in,
                              void* d_out, int out_size) {
    const float4* x4   = (const float4*)d_in[0];  // [16,20] fp32, 320 elems
    const float* theta = (const float*)d_in[1];   // [20] fp32
    float4* out4 = (float4*)d_out;                // [16,20] fp32
    qfe_kernel<<<1, NTHREADS>>>(x4, theta, out4);
}